// round 17
// baseline (speedup 1.0000x reference)
#include <cuda_runtime.h>
#include <cuda_bf16.h>
#include <cstdint>

#define N_NODES 100000
#define N_EDGES 640000
#define D 128
#define NB 391   // ceil(N_NODES/256)

// ======================= PTX helpers ========================================
__device__ __forceinline__ uint32_t smem_u32(const void* p) {
    uint32_t a;
    asm("{ .reg .u64 t; cvta.to.shared.u64 t, %1; cvt.u32.u64 %0, t; }"
        : "=r"(a) : "l"(p));
    return a;
}
#define LDSM_X4(r0, r1, r2, r3, addr) \
    asm volatile("ldmatrix.sync.aligned.m8n8.x4.shared.b16 {%0,%1,%2,%3}, [%4];" \
        : "=r"(r0), "=r"(r1), "=r"(r2), "=r"(r3) : "r"(addr))
#define LDSM_X2(r0, r1, addr) \
    asm volatile("ldmatrix.sync.aligned.m8n8.x2.shared.b16 {%0,%1}, [%2];" \
        : "=r"(r0), "=r"(r1) : "r"(addr))
#define MMA_BF16(c, a, b0, b1) \
    asm volatile("mma.sync.aligned.m16n8k16.row.col.f32.bf16.bf16.f32 " \
        "{%0,%1,%2,%3},{%4,%5,%6,%7},{%8,%9},{%0,%1,%2,%3};" \
        : "+f"((c)[0]), "+f"((c)[1]), "+f"((c)[2]), "+f"((c)[3]) \
        : "r"((a)[0]), "r"((a)[1]), "r"((a)[2]), "r"((a)[3]), "r"(b0), "r"(b1))
#define CP_ASYNC16(dst, src) \
    asm volatile("cp.async.ca.shared.global [%0], [%1], 16;" \
        :: "r"(dst), "l"(src) : "memory")
#define CP_COMMIT() asm volatile("cp.async.commit_group;" ::: "memory")
#define CP_WAIT(n)  asm volatile("cp.async.wait_group %0;" :: "n"(n) : "memory")

__device__ __forceinline__ uint32_t pack_bf16(__nv_bfloat16 lo, __nv_bfloat16 hi) {
    return ((uint32_t)__bfloat16_as_ushort(hi) << 16) |
           (uint32_t)__bfloat16_as_ushort(lo);
}
__device__ __forceinline__ void acc_bf2(uint32_t w, float& x, float& y) {
    __nv_bfloat162 b = *reinterpret_cast<__nv_bfloat162*>(&w);
    float2 f = __bfloat1622float2(b);
    x += f.x; y += f.y;
}

// ======================= scratch globals ====================================
// features / h as bf16 hi+lo; aggregation output as bf16 hi+lo
__device__ __align__(16) __nv_bfloat16 g_fhi[(size_t)N_NODES * D];  // 25.6 MB
__device__ __align__(16) __nv_bfloat16 g_flo[(size_t)N_NODES * D];
__device__ __align__(16) __nv_bfloat16 g_ahi[(size_t)N_NODES * D];
__device__ __align__(16) __nv_bfloat16 g_alo[(size_t)N_NODES * D];
__device__ int   g_cnt[N_NODES];
__device__ float g_rcnt[N_NODES];
__device__ int   g_rowptr[N_NODES];
__device__ int   g_excl[N_NODES];
__device__ int   g_cursor[N_NODES];
__device__ int   g_srcs[N_EDGES];
__device__ int   g_bsum[512];
__device__ int   g_boff[512];
__device__ __align__(16) __nv_bfloat16 g_whi[4 * 16384];   // Wl1,Wr1,Wl2,Wr2 hi
__device__ __align__(16) __nv_bfloat16 g_wlo[4 * 16384];   // lo residuals

// ======================= CSR build ==========================================
__global__ void zero_cnt_kernel() {
    int i = blockIdx.x * blockDim.x + threadIdx.x;
    if (i < N_NODES) g_cnt[i] = 0;
}
__global__ void count_kernel(const int* __restrict__ ei) {
    int e = blockIdx.x * blockDim.x + threadIdx.x;
    if (e < N_EDGES) atomicAdd(&g_cnt[ei[N_EDGES + e]], 1);
}
__global__ void scan_local_kernel() {
    __shared__ int s[256];
    int i = blockIdx.x * 256 + threadIdx.x;
    int v = (i < N_NODES) ? g_cnt[i] : 0;
    s[threadIdx.x] = v;
    __syncthreads();
#pragma unroll
    for (int off = 1; off < 256; off <<= 1) {
        int t = (threadIdx.x >= off) ? s[threadIdx.x - off] : 0;
        __syncthreads();
        s[threadIdx.x] += t;
        __syncthreads();
    }
    if (i < N_NODES) g_excl[i] = s[threadIdx.x] - v;
    if (threadIdx.x == 255) g_bsum[blockIdx.x] = s[255];
}
__global__ void scan_bsums_kernel() {
    __shared__ int s[512];
    int v = (threadIdx.x < NB) ? g_bsum[threadIdx.x] : 0;
    s[threadIdx.x] = v;
    __syncthreads();
#pragma unroll
    for (int off = 1; off < 512; off <<= 1) {
        int t = (threadIdx.x >= off) ? s[threadIdx.x - off] : 0;
        __syncthreads();
        s[threadIdx.x] += t;
        __syncthreads();
    }
    if (threadIdx.x < NB) g_boff[threadIdx.x] = s[threadIdx.x] - v;
}
__global__ void scan_add_kernel() {      // also produces rcnt
    int i = blockIdx.x * 256 + threadIdx.x;
    if (i < N_NODES) {
        int r = g_excl[i] + g_boff[blockIdx.x];
        g_rowptr[i] = r;
        g_cursor[i] = r;
        g_rcnt[i] = 1.0f / fmaxf((float)g_cnt[i], 1.0f);
    }
}
__global__ void fill_src_kernel(const int* __restrict__ ei) {
    int e = blockIdx.x * blockDim.x + threadIdx.x;
    if (e < N_EDGES) {
        int d = ei[N_EDGES + e];
        int pos = atomicAdd(&g_cursor[d], 1);
        g_srcs[pos] = ei[e];
    }
}

// ======================= pre-split: weights and x -> bf16 hi/lo ============
__global__ void wprep_kernel(const float* __restrict__ Wl1, const float* __restrict__ Wr1,
                             const float* __restrict__ Wl2, const float* __restrict__ Wr2) {
    int i = blockIdx.x * 256 + threadIdx.x;     // 0..65535
    int m = i >> 14, r = i & 16383;
    const float* W = (m == 0) ? Wl1 : (m == 1) ? Wr1 : (m == 2) ? Wl2 : Wr2;
    float x = W[r];
    __nv_bfloat16 h = __float2bfloat16(x);
    g_whi[i] = h;
    g_wlo[i] = __float2bfloat16(x - __bfloat162float(h));
}
__global__ void xprep_kernel(const float* __restrict__ x) {
    size_t t = (size_t)blockIdx.x * 256 + threadIdx.x;   // one float4 group
    if (t >= (size_t)N_NODES * D / 4) return;
    float4 v = reinterpret_cast<const float4*>(x)[t];
    __nv_bfloat16 h0 = __float2bfloat16(v.x), h1 = __float2bfloat16(v.y);
    __nv_bfloat16 h2 = __float2bfloat16(v.z), h3 = __float2bfloat16(v.w);
    uint2 hw, lw;
    hw.x = pack_bf16(h0, h1);
    hw.y = pack_bf16(h2, h3);
    lw.x = pack_bf16(__float2bfloat16(v.x - __bfloat162float(h0)),
                     __float2bfloat16(v.y - __bfloat162float(h1)));
    lw.y = pack_bf16(__float2bfloat16(v.z - __bfloat162float(h2)),
                     __float2bfloat16(v.w - __bfloat162float(h3)));
    reinterpret_cast<uint2*>(g_fhi)[t] = hw;
    reinterpret_cast<uint2*>(g_flo)[t] = lw;
}

// ======================= aggregation: warp-per-node gather (bf16 hi/lo) ====
__global__ __launch_bounds__(256)
void agg_kernel() {
    int node = blockIdx.x * 8 + (threadIdx.x >> 5);
    int lane = threadIdx.x & 31;
    if (node >= N_NODES) return;
    int beg = g_rowptr[node];
    int end = beg + g_cnt[node];
    const size_t lo4 = (size_t)lane * 4;

    float a0 = 0.f, a1 = 0.f, a2 = 0.f, a3 = 0.f;
    int p = beg;
    for (; p + 3 < end; p += 4) {
        int s0 = g_srcs[p],     s1 = g_srcs[p + 1];
        int s2 = g_srcs[p + 2], s3 = g_srcs[p + 3];
        uint2 h0 = *reinterpret_cast<const uint2*>(g_fhi + (size_t)s0 * D + lo4);
        uint2 l0 = *reinterpret_cast<const uint2*>(g_flo + (size_t)s0 * D + lo4);
        uint2 h1 = *reinterpret_cast<const uint2*>(g_fhi + (size_t)s1 * D + lo4);
        uint2 l1 = *reinterpret_cast<const uint2*>(g_flo + (size_t)s1 * D + lo4);
        uint2 h2 = *reinterpret_cast<const uint2*>(g_fhi + (size_t)s2 * D + lo4);
        uint2 l2 = *reinterpret_cast<const uint2*>(g_flo + (size_t)s2 * D + lo4);
        uint2 h3 = *reinterpret_cast<const uint2*>(g_fhi + (size_t)s3 * D + lo4);
        uint2 l3 = *reinterpret_cast<const uint2*>(g_flo + (size_t)s3 * D + lo4);
        acc_bf2(h0.x, a0, a1); acc_bf2(h0.y, a2, a3);
        acc_bf2(l0.x, a0, a1); acc_bf2(l0.y, a2, a3);
        acc_bf2(h1.x, a0, a1); acc_bf2(h1.y, a2, a3);
        acc_bf2(l1.x, a0, a1); acc_bf2(l1.y, a2, a3);
        acc_bf2(h2.x, a0, a1); acc_bf2(h2.y, a2, a3);
        acc_bf2(l2.x, a0, a1); acc_bf2(l2.y, a2, a3);
        acc_bf2(h3.x, a0, a1); acc_bf2(h3.y, a2, a3);
        acc_bf2(l3.x, a0, a1); acc_bf2(l3.y, a2, a3);
    }
    for (; p < end; ++p) {
        int s0 = g_srcs[p];
        uint2 h0 = *reinterpret_cast<const uint2*>(g_fhi + (size_t)s0 * D + lo4);
        uint2 l0 = *reinterpret_cast<const uint2*>(g_flo + (size_t)s0 * D + lo4);
        acc_bf2(h0.x, a0, a1); acc_bf2(h0.y, a2, a3);
        acc_bf2(l0.x, a0, a1); acc_bf2(l0.y, a2, a3);
    }
    float r = g_rcnt[node];
    a0 *= r; a1 *= r; a2 *= r; a3 *= r;
    __nv_bfloat16 h0 = __float2bfloat16(a0), h1 = __float2bfloat16(a1);
    __nv_bfloat16 h2 = __float2bfloat16(a2), h3 = __float2bfloat16(a3);
    uint2 hw, lw;
    hw.x = pack_bf16(h0, h1);
    hw.y = pack_bf16(h2, h3);
    lw.x = pack_bf16(__float2bfloat16(a0 - __bfloat162float(h0)),
                     __float2bfloat16(a1 - __bfloat162float(h1)));
    lw.y = pack_bf16(__float2bfloat16(a2 - __bfloat162float(h2)),
                     __float2bfloat16(a3 - __bfloat162float(h3)));
    *reinterpret_cast<uint2*>(g_ahi + (size_t)node * D + lo4) = hw;
    *reinterpret_cast<uint2*>(g_alo + (size_t)node * D + lo4) = lw;
}

// ======================= cp.async bf16-split mma GEMM ======================
// out[128n x 128j] = [agg | feat] (K=256) @ [Wl | Wr]^T + bias, row-normalized.
// All operands bf16 hi/lo in global; k-loop is pure cp.async -> smem, double
// buffered. 3-MMA emulated fp32: Ah*Bh + Ah*Bl + Al*Bh.
// LAST=false: ReLU + write h back to g_fhi/g_flo. LAST=true: fp32 to out.
constexpr int TILE_B   = 10240;           // 128 rows x 80B (16B-pad, LDSM-safe)
constexpr int STAGE_B  = 4 * TILE_B;      // Ah, Al, Bh, Bl
constexpr int GSMEM    = 2 * STAGE_B;     // 81920

template <bool LAST>
__global__ __launch_bounds__(256, 2)
void gemm_ca_kernel(const float* __restrict__ bl,
                    int woff,
                    float* __restrict__ out) {
    extern __shared__ __align__(128) char dyn[];
    __shared__ float sb[128];
    __shared__ float sm_ss[2][128];

    const int tid  = threadIdx.x;
    const int wid  = tid >> 5;
    const int lane = tid & 31;
    const int wm   = wid & 3;            // row group (32 rows)
    const int wn   = wid >> 2;           // col group (64 cols)
    const int n0   = blockIdx.x * 128;

    if (tid < 128) sb[tid] = __ldg(bl + tid);

    const uint32_t base = smem_u32(dyn);

    // cp.async mapping: thread t -> row t>>1, chunk pair (t&1)*2
    const int prow = tid >> 1;
    const int pc0  = (tid & 1) * 2;
    const int pn   = n0 + prow;
    const int pncl = (pn < N_NODES) ? pn : (N_NODES - 1);

    auto prefetch = [&](int kt, int stage) {
        const uint32_t sbs = base + stage * STAGE_B + prow * 80;
        const int gk = (kt & 3) * 32;
        const __nv_bfloat16* Ah = (kt < 4) ? g_ahi : g_fhi;
        const __nv_bfloat16* Al = (kt < 4) ? g_alo : g_flo;
        const int wb = woff + ((kt >= 4) ? 16384 : 0);
        const size_t arow = (size_t)pncl * D + gk;
        const int    brow = wb + prow * D + gk;
#pragma unroll
        for (int q = 0; q < 2; ++q) {
            int c = pc0 + q;
            CP_ASYNC16(sbs + c * 16,              Ah + arow + c * 8);
            CP_ASYNC16(sbs + TILE_B + c * 16,     Al + arow + c * 8);
            CP_ASYNC16(sbs + 2 * TILE_B + c * 16, g_whi + brow + c * 8);
            CP_ASYNC16(sbs + 3 * TILE_B + c * 16, g_wlo + brow + c * 8);
        }
        CP_COMMIT();
    };

    float c[2][8][4];
#pragma unroll
    for (int mt = 0; mt < 2; ++mt)
#pragma unroll
        for (int nt = 0; nt < 8; ++nt)
#pragma unroll
            for (int q = 0; q < 4; ++q) c[mt][nt][q] = 0.f;

    prefetch(0, 0);

#pragma unroll 1
    for (int kt = 0; kt < 8; ++kt) {
        if (kt < 7) prefetch(kt + 1, (kt + 1) & 1);
        if (kt < 7) { CP_WAIT(1); } else { CP_WAIT(0); }
        __syncthreads();

        const uint32_t uAh = base + (kt & 1) * STAGE_B;
        const uint32_t uAl = uAh + TILE_B;
        const uint32_t uBh = uAh + 2 * TILE_B;
        const uint32_t uBl = uAh + 3 * TILE_B;

#pragma unroll
        for (int kk = 0; kk < 2; ++kk) {
            uint32_t ah[2][4], al[2][4];
#pragma unroll
            for (int mt = 0; mt < 2; ++mt) {
                uint32_t ar = (uint32_t)((wm * 32 + mt * 16 + (lane & 15)) * 80
                                         + kk * 32 + (lane >> 4) * 16);
                LDSM_X4(ah[mt][0], ah[mt][1], ah[mt][2], ah[mt][3], uAh + ar);
                LDSM_X4(al[mt][0], al[mt][1], al[mt][2], al[mt][3], uAl + ar);
            }
            const int ln = lane & 15;
#pragma unroll
            for (int nt = 0; nt < 8; ++nt) {
                uint32_t br = (uint32_t)((wn * 64 + nt * 8 + (ln & 7)) * 80
                                         + kk * 32 + (ln >> 3) * 16);
                uint32_t bh0, bh1, bl0, bl1;
                LDSM_X2(bh0, bh1, uBh + br);
                LDSM_X2(bl0, bl1, uBl + br);
#pragma unroll
                for (int mt = 0; mt < 2; ++mt) {
                    MMA_BF16(c[mt][nt], ah[mt], bh0, bh1);
                    MMA_BF16(c[mt][nt], ah[mt], bl0, bl1);
                    MMA_BF16(c[mt][nt], al[mt], bh0, bh1);
                }
            }
        }
        __syncthreads();
    }

    // ---- epilogue: bias, row SS, normalize, (relu), store ----
    float ssA[2] = {0.f, 0.f}, ssB[2] = {0.f, 0.f};
#pragma unroll
    for (int mt = 0; mt < 2; ++mt)
#pragma unroll
        for (int nt = 0; nt < 8; ++nt) {
            int cb = wn * 64 + nt * 8 + 2 * (lane & 3);
            float b0 = sb[cb], b1 = sb[cb + 1];
            c[mt][nt][0] += b0; c[mt][nt][1] += b1;
            c[mt][nt][2] += b0; c[mt][nt][3] += b1;
            ssA[mt] += c[mt][nt][0] * c[mt][nt][0] + c[mt][nt][1] * c[mt][nt][1];
            ssB[mt] += c[mt][nt][2] * c[mt][nt][2] + c[mt][nt][3] * c[mt][nt][3];
        }
#pragma unroll
    for (int m = 1; m < 4; m <<= 1)
#pragma unroll
        for (int mt = 0; mt < 2; ++mt) {
            ssA[mt] += __shfl_xor_sync(0xffffffffu, ssA[mt], m);
            ssB[mt] += __shfl_xor_sync(0xffffffffu, ssB[mt], m);
        }
    if ((lane & 3) == 0) {
#pragma unroll
        for (int mt = 0; mt < 2; ++mt) {
            int rA = wm * 32 + mt * 16 + (lane >> 2);
            sm_ss[wn][rA]     = ssA[mt];
            sm_ss[wn][rA + 8] = ssB[mt];
        }
    }
    __syncthreads();

#pragma unroll
    for (int mt = 0; mt < 2; ++mt) {
#pragma unroll
        for (int half = 0; half < 2; ++half) {
            int r  = wm * 32 + mt * 16 + (lane >> 2) + half * 8;
            int qo = half * 2;     // c[][][qo], c[][][qo+1]
            if (n0 + r >= N_NODES) continue;
            float inv = 1.0f / fmaxf(sqrtf(sm_ss[0][r] + sm_ss[1][r]), 1e-12f);
#pragma unroll
            for (int nt = 0; nt < 8; ++nt) {
                int cb = wn * 64 + nt * 8 + 2 * (lane & 3);
                float w0 = c[mt][nt][qo]     * inv;
                float w1 = c[mt][nt][qo + 1] * inv;
                if (LAST) {
                    float2 w = make_float2(w0, w1);
                    *reinterpret_cast<float2*>(out + (size_t)(n0 + r) * D + cb) = w;
                } else {
                    w0 = fmaxf(w0, 0.f);
                    w1 = fmaxf(w1, 0.f);
                    __nv_bfloat16 h0 = __float2bfloat16(w0);
                    __nv_bfloat16 h1 = __float2bfloat16(w1);
                    size_t o = (size_t)(n0 + r) * D + cb;
                    *reinterpret_cast<uint32_t*>(g_fhi + o) = pack_bf16(h0, h1);
                    *reinterpret_cast<uint32_t*>(g_flo + o) =
                        pack_bf16(__float2bfloat16(w0 - __bfloat162float(h0)),
                                  __float2bfloat16(w1 - __bfloat162float(h1)));
                }
            }
        }
    }
}

// ======================= launch =============================================
extern "C" void kernel_launch(void* const* d_in, const int* in_sizes, int n_in,
                              void* d_out, int out_size) {
    const float* x   = (const float*)d_in[0];
    const int*   ei  = (const int*)d_in[1];     // int32 (JAX x64 disabled)
    const float* Wl1 = (const float*)d_in[2];
    const float* bl1 = (const float*)d_in[3];
    const float* Wr1 = (const float*)d_in[4];
    const float* Wl2 = (const float*)d_in[5];
    const float* bl2 = (const float*)d_in[6];
    const float* Wr2 = (const float*)d_in[7];
    float* out = (float*)d_out;

    const int eblocks = (N_EDGES + 255) / 256;   // 2500
    const int ablocks = (N_NODES + 7) / 8;       // 12500 (warp/node)
    const int gblocks = (N_NODES + 127) / 128;   // 782
    const int xblocks = (N_NODES * D / 4 + 255) / 256;   // 12500

    cudaFuncSetAttribute(gemm_ca_kernel<false>,
                         cudaFuncAttributeMaxDynamicSharedMemorySize, GSMEM);
    cudaFuncSetAttribute(gemm_ca_kernel<true>,
                         cudaFuncAttributeMaxDynamicSharedMemorySize, GSMEM);

    // CSR build + operand pre-split (layer-invariant)
    zero_cnt_kernel<<<NB, 256>>>();
    count_kernel<<<eblocks, 256>>>(ei);
    scan_local_kernel<<<NB, 256>>>();
    scan_bsums_kernel<<<1, 512>>>();
    scan_add_kernel<<<NB, 256>>>();
    fill_src_kernel<<<eblocks, 256>>>(ei);
    wprep_kernel<<<256, 256>>>(Wl1, Wr1, Wl2, Wr2);
    xprep_kernel<<<xblocks, 256>>>(x);

    // Layer 1: agg(feat) -> gemm -> feat (h, ReLU, bf16 hi/lo)
    agg_kernel<<<ablocks, 256>>>();
    gemm_ca_kernel<false><<<gblocks, 256, GSMEM>>>(bl1, 0, nullptr);

    // Layer 2: agg(h) -> gemm -> out (fp32)
    agg_kernel<<<ablocks, 256>>>();
    gemm_ca_kernel<true><<<gblocks, 256, GSMEM>>>(bl2, 32768, out);
}